// round 17
// baseline (speedup 1.0000x reference)
#include <cuda_runtime.h>
#include <cuda_bf16.h>
#include <math.h>
#include <stdint.h>

#define D       128
#define KCLUST  1024
#define BM      128        // points per CTA
#define NSTAGE  8          // 8 x 128 clusters
#define NT      256
#define MAXN    262144

// smem layout (bytes)
#define SM_B0     0          // B stage buffer 0 (32KB)
#define SM_B1     32768      // B stage buffer 1 (32KB)
#define SM_RAW    65536      // raw X tile fp32  (64KB)
#define SM_CCOFF  131072     // CC (4KB)
#define SMEM_TOTAL (SM_CCOFF + KCLUST * 4)

#define B_STAGE_BYTES 32768

__device__ float g_CC[KCLUST];
// B bf16 fragments: [stage][ks 0..7][nf 0..15][lane 0..31] x uint2 {b0,b1}
__device__ __align__(16) uint2 g_Bperm[NSTAGE * 8 * 16 * 32];
__device__ int4 g_top4[MAXN];
// 16B-aligned scatter accumulator: [w_sum(K*D) | xw_sum(K*D)]
__device__ __align__(16) float g_acc[2 * KCLUST * D];

// ---------------------------------------------------------------------------
__device__ __forceinline__ uint32_t pack_bf16x2(float lo, float hi) {
    __nv_bfloat162 v = __floats2bfloat162_rn(lo, hi);   // x=lo -> low 16 bits
    return *(uint32_t*)&v;
}
__device__ __forceinline__ uint32_t smem_u32(const void* p) {
    return (uint32_t)__cvta_generic_to_shared(p);
}
__device__ __forceinline__ void cp_async16(uint32_t dst, const void* src) {
    asm volatile("cp.async.cg.shared.global [%0], [%1], 16;" :: "r"(dst), "l"(src));
}
#define CP_COMMIT() asm volatile("cp.async.commit_group;" ::: "memory")
#define CP_WAIT(n)  asm volatile("cp.async.wait_group %0;" :: "n"(n) : "memory")

__device__ __forceinline__ void mma_bf16(float* c, const uint4& a,
                                         uint32_t b0, uint32_t b1) {
    asm volatile(
        "mma.sync.aligned.m16n8k16.row.col.f32.bf16.bf16.f32 "
        "{%0,%1,%2,%3}, {%4,%5,%6,%7}, {%8,%9}, {%0,%1,%2,%3};"
        : "+f"(c[0]), "+f"(c[1]), "+f"(c[2]), "+f"(c[3])
        : "r"(a.x), "r"(a.y), "r"(a.z), "r"(a.w), "r"(b0), "r"(b1));
}

// Vector fp32 reduction to global (16B-aligned destination required)
__device__ __forceinline__ void red_add_v4(float* gptr, float4 v) {
    asm volatile("red.global.add.v4.f32 [%0], {%1, %2, %3, %4};"
                 :: "l"(gptr), "f"(v.x), "f"(v.y), "f"(v.z), "f"(v.w)
                 : "memory");
}

// ---------------------------------------------------------------------------
// Prep: zero output + scratch accumulator; CC[k]; build bf16 g_Bperm.
// ---------------------------------------------------------------------------
__global__ void prep_kernel(const float* __restrict__ C,
                            float* __restrict__ out, int total_out) {
    int tid  = blockIdx.x * blockDim.x + threadIdx.x;
    int nthr = gridDim.x * blockDim.x;
    for (int i = tid; i < total_out; i += nthr) out[i] = 0.0f;
    for (int i = tid; i < 2 * KCLUST * D / 4; i += nthr)
        ((float4*)g_acc)[i] = make_float4(0.f, 0.f, 0.f, 0.f);

    int warp = tid >> 5;
    int lane = tid & 31;
    if (warp < KCLUST) {
        const float4* row = (const float4*)(C + (size_t)warp * D);
        float4 v = row[lane];
        float s = v.x * v.x + v.y * v.y + v.z * v.z + v.w * v.w;
        #pragma unroll
        for (int o = 16; o > 0; o >>= 1) s += __shfl_xor_sync(0xffffffffu, s, o);
        if (lane == 0) g_CC[warp] = s;
    }

    // e: [stage(3b) | ks(3b) | nf(4b) | lane(5b)]  -> 32768 uint2
    for (int e = tid; e < NSTAGE * 8 * 16 * 32; e += nthr) {
        int l  = e & 31;
        int nf = (e >> 5) & 15;
        int ks = (e >> 9) & 7;
        int st = e >> 12;
        int cl = st * 128 + nf * 8 + (l >> 2);
        int k0 = ks * 16 + (l & 3) * 2;
        const float* cr = C + (size_t)cl * D;
        uint2 v;
        v.x = pack_bf16x2(cr[k0],     cr[k0 + 1]);      // k rows k0, k0+1
        v.y = pack_bf16x2(cr[k0 + 8], cr[k0 + 9]);      // k rows k0+8, k0+9
        g_Bperm[e] = v;
    }
}

// ---------------------------------------------------------------------------
// Assign: bf16 mma.sync m16n8k16, CTA = 128 points x 1024 clusters (8 stages).
// Warp grid 4x2; A fragments in registers; top-2 per thread, merged to a
// TOP-4 candidate set per point for exact fp32 rescoring.
// ---------------------------------------------------------------------------
__global__ __launch_bounds__(NT, 1)
void assign_kernel(const float* __restrict__ X) {
    extern __shared__ char smem[];
    const uint32_t sbase = smem_u32(smem);
    const int tid  = threadIdx.x;
    const int lane = tid & 31;
    const int wid  = tid >> 5;
    const int rg   = wid >> 1;       // row-group (0..3), 32 rows each
    const int cg   = wid & 1;        // col-group (0..1), 64 cols each
    const int n0   = blockIdx.x * BM;
    float* cc_s = (float*)(smem + SM_CCOFF);

    // ---- stage raw X tile (fp32, coalesced float4) ----
    {
        float4* raw = (float4*)(smem + SM_RAW);
        #pragma unroll
        for (int j = 0; j < 16; j++) {
            int idx = tid + j * NT;            // 4096 float4
            int row = idx >> 5, c4 = idx & 31;
            raw[idx] = ((const float4*)(X + (size_t)(n0 + row) * D))[c4];
        }
    }
    for (int i = tid; i < KCLUST; i += NT) cc_s[i] = g_CC[i];
    __syncthreads();

    // ---- build this warp's A fragments in registers (one-time) ----
    uint4 av[2][8];
    {
        const float* raw = (const float*)(smem + SM_RAW);
        #pragma unroll
        for (int ks = 0; ks < 8; ks++)
            #pragma unroll
            for (int mf = 0; mf < 2; mf++) {
                int row = rg * 32 + mf * 16 + (lane >> 2);
                int k0  = ks * 16 + (lane & 3) * 2;
                float2 p00 = *(const float2*)(raw + row * D + k0);
                float2 p10 = *(const float2*)(raw + (row + 8) * D + k0);
                float2 p01 = *(const float2*)(raw + row * D + k0 + 8);
                float2 p11 = *(const float2*)(raw + (row + 8) * D + k0 + 8);
                av[mf][ks].x = pack_bf16x2(p00.x, p00.y);
                av[mf][ks].y = pack_bf16x2(p10.x, p10.y);
                av[mf][ks].z = pack_bf16x2(p01.x, p01.y);
                av[mf][ks].w = pack_bf16x2(p11.x, p11.y);
            }
    }

    // ---- prefetch stage 0 into SM_B0 ----
    {
        const char* src = (const char*)g_Bperm;
        #pragma unroll
        for (int j = 0; j < 8; j++) {
            int c = tid + j * NT;              // 2048 x 16B
            cp_async16(sbase + SM_B0 + c * 16, src + (size_t)c * 16);
        }
        CP_COMMIT();
    }

    // persistent top-2 per owned row (4 rows: mf*2 + h)
    float tb1[4], tb2[4];
    int   ti1[4], ti2[4];
    #pragma unroll
    for (int i = 0; i < 4; i++) { tb1[i] = 3.4e38f; tb2[i] = 3.4e38f; ti1[i] = 0; ti2[i] = 1; }

    for (int s = 0; s < NSTAGE; s++) {
        // prefetch next stage
        if (s + 1 < NSTAGE) {
            uint32_t bb = sbase + (((s + 1) & 1) ? SM_B1 : SM_B0);
            const char* src = (const char*)g_Bperm + (size_t)(s + 1) * B_STAGE_BYTES;
            #pragma unroll
            for (int j = 0; j < 8; j++) {
                int c = tid + j * NT;
                cp_async16(bb + c * 16, src + (size_t)c * 16);
            }
            CP_COMMIT();
            CP_WAIT(1);
        } else {
            CP_WAIT(0);
        }
        __syncthreads();

        const uint2* Bb = (const uint2*)(smem + ((s & 1) ? SM_B1 : SM_B0));

        float acc[2][8][4];
        #pragma unroll
        for (int mf = 0; mf < 2; mf++)
            #pragma unroll
            for (int nf = 0; nf < 8; nf++)
                #pragma unroll
                for (int r = 0; r < 4; r++) acc[mf][nf][r] = 0.0f;

        #pragma unroll
        for (int ks = 0; ks < 8; ks++) {
            uint2 bv[8];
            #pragma unroll
            for (int nf = 0; nf < 8; nf++)
                bv[nf] = Bb[(ks * 16 + cg * 8 + nf) * 32 + lane];
            #pragma unroll
            for (int nf = 0; nf < 8; nf++)
                #pragma unroll
                for (int mf = 0; mf < 2; mf++)
                    mma_bf16(acc[mf][nf], av[mf][ks], bv[nf].x, bv[nf].y);
        }

        // fold tile into top-2:  m = CC - 2*dot
        #pragma unroll
        for (int nf = 0; nf < 8; nf++) {
            int colb = s * 128 + cg * 64 + nf * 8 + 2 * (lane & 3);
            float cc0 = cc_s[colb], cc1 = cc_s[colb + 1];
            #pragma unroll
            for (int mf = 0; mf < 2; mf++) {
                #pragma unroll
                for (int h = 0; h < 2; h++) {
                    int r = mf * 2 + h;
                    float m0 = fmaf(-2.0f, acc[mf][nf][h * 2 + 0], cc0);
                    float m1 = fmaf(-2.0f, acc[mf][nf][h * 2 + 1], cc1);
                    if (m0 < tb1[r]) { tb2[r] = tb1[r]; ti2[r] = ti1[r]; tb1[r] = m0; ti1[r] = colb; }
                    else if (m0 < tb2[r]) { tb2[r] = m0; ti2[r] = colb; }
                    if (m1 < tb1[r]) { tb2[r] = tb1[r]; ti2[r] = ti1[r]; tb1[r] = m1; ti1[r] = colb + 1; }
                    else if (m1 < tb2[r]) { tb2[r] = m1; ti2[r] = colb + 1; }
                }
            }
        }
        __syncthreads();   // buffer reuse guard
    }

    // ---- cross-warp merge to TOP-4 (B buffers now dead) ----
    float4* red = (float4*)(smem + SM_B0);   // [row 0..127][cand 0..7]
    #pragma unroll
    for (int mf = 0; mf < 2; mf++)
        #pragma unroll
        for (int h = 0; h < 2; h++) {
            int r   = mf * 2 + h;
            int row = rg * 32 + mf * 16 + h * 8 + (lane >> 2);
            red[row * 8 + cg * 4 + (lane & 3)] =
                make_float4(tb1[r], tb2[r], __int_as_float(ti1[r]), __int_as_float(ti2[r]));
        }
    __syncthreads();

    if (tid < BM) {
        float b[4] = {3.4e38f, 3.4e38f, 3.4e38f, 3.4e38f};
        int   bi[4] = {0, 1, 2, 3};
        #pragma unroll
        for (int c = 0; c < 8; c++) {
            float4 v = red[tid * 8 + c];
            #pragma unroll
            for (int t = 0; t < 2; t++) {
                float nv = (t == 0) ? v.x : v.y;
                int   ni = __float_as_int((t == 0) ? v.z : v.w);
                if (nv < b[3]) {
                    b[3] = nv; bi[3] = ni;
                    if (b[3] < b[2]) { float tv=b[2]; b[2]=b[3]; b[3]=tv; int tx=bi[2]; bi[2]=bi[3]; bi[3]=tx; }
                    if (b[2] < b[1]) { float tv=b[1]; b[1]=b[2]; b[2]=tv; int tx=bi[1]; bi[1]=bi[2]; bi[2]=tx; }
                    if (b[1] < b[0]) { float tv=b[0]; b[0]=b[1]; b[1]=tv; int tx=bi[0]; bi[0]=bi[1]; bi[1]=tx; }
                }
            }
        }
        g_top4[n0 + tid] = make_int4(bi[0], bi[1], bi[2], bi[3]);
    }
}

// ---------------------------------------------------------------------------
// Rescore + scatter: one warp per point; exact fp32 d^2 for 4 candidates,
// pick winner, inertia, then 2 x red.global.add.v4.f32 into aligned scratch.
// ---------------------------------------------------------------------------
__global__ __launch_bounds__(256)
void rescore_scatter(const float* __restrict__ X,
                     const float* __restrict__ SW,
                     const float* __restrict__ C,
                     float* __restrict__ out) {
    __shared__ float sred[8];
    const int wid  = threadIdx.x >> 5;
    const int lane = threadIdx.x & 31;
    const int p    = blockIdx.x * 8 + wid;

    int4 cand = g_top4[p];
    int ci[4] = {cand.x, cand.y, cand.z, cand.w};

    float4 x = ((const float4*)(X  + (size_t)p * D))[lane];
    float4 s = ((const float4*)(SW + (size_t)p * D))[lane];

    float d[4];
    #pragma unroll
    for (int j = 0; j < 4; j++) {
        float4 c = ((const float4*)(C + (size_t)ci[j] * D))[lane];
        float dx, acc = 0.0f;
        dx = x.x - c.x; acc += dx * dx;  dx = x.y - c.y; acc += dx * dx;
        dx = x.z - c.z; acc += dx * dx;  dx = x.w - c.w; acc += dx * dx;
        d[j] = acc;
    }
    #pragma unroll
    for (int o = 16; o > 0; o >>= 1) {
        #pragma unroll
        for (int j = 0; j < 4; j++)
            d[j] += __shfl_xor_sync(0xffffffffu, d[j], o);
    }

    int   y    = ci[0];
    float dmin = d[0];
    #pragma unroll
    for (int j = 1; j < 4; j++) {
        if (d[j] < dmin || (d[j] == dmin && ci[j] < y)) { dmin = d[j]; y = ci[j]; }
    }
    if (lane == 0) sred[wid] = sqrtf(fmaxf(dmin, 0.0f));

    float* wd = g_acc + (size_t)y * D + lane * 4;
    float* xd = g_acc + (size_t)KCLUST * D + (size_t)y * D + lane * 4;
    red_add_v4(wd, s);
    red_add_v4(xd, make_float4(x.x * s.x, x.y * s.y, x.z * s.z, x.w * s.w));

    __syncthreads();
    if (threadIdx.x == 0) {
        float acc = 0.0f;
        #pragma unroll
        for (int i = 0; i < 8; i++) acc += sred[i];
        atomicAdd(out, acc);
    }
}

// ---------------------------------------------------------------------------
// Tail: copy scratch accumulator into the (misaligned-by-1) output region.
// ---------------------------------------------------------------------------
__global__ void finalize_kernel(float* __restrict__ out) {
    int i = blockIdx.x * blockDim.x + threadIdx.x;
    if (i < 2 * KCLUST * D / 4) {
        float4 v = ((const float4*)g_acc)[i];
        float* o = out + 1 + i * 4;
        o[0] = v.x; o[1] = v.y; o[2] = v.z; o[3] = v.w;
    }
}

// ---------------------------------------------------------------------------
extern "C" void kernel_launch(void* const* d_in, const int* in_sizes, int n_in,
                              void* d_out, int out_size) {
    const float* X  = (const float*)d_in[0];
    const float* SW = (const float*)d_in[1];
    const float* C  = (const float*)d_in[2];
    float* out = (float*)d_out;
    const int N = in_sizes[0] / D;

    cudaFuncSetAttribute(assign_kernel,
                         cudaFuncAttributeMaxDynamicSharedMemorySize, SMEM_TOTAL);

    prep_kernel<<<256, 256>>>(C, out, out_size);
    assign_kernel<<<N / BM, NT, SMEM_TOTAL>>>(X);
    rescore_scatter<<<N / 8, 256>>>(X, SW, C, out);
    finalize_kernel<<<(2 * KCLUST * D / 4 + 255) / 256, 256>>>(out);
}